// round 2
// baseline (speedup 1.0000x reference)
#include <cuda_runtime.h>

typedef unsigned long long ull;

#define D_DIM 11008
#define K_DIM 172
#define M_DIM 64
#define THREADS 512
#define JT 16          // had_K j-tile width
#define NT 11          // ceil(172/16)
#define TI 6           // output rows (i) per thread
#define TM 8           // output cols (m) per thread

// smem layout (floats):
//   xs  : 2*11008 data + 256 zero pad           = 22272
//   hkd : 2 double-buffers of duplicated had_K tile, stride 354 floats per jj,
//         buffer size 5696 floats each          = 11392
#define XS_FLOATS   22272
#define HK_BUF      5696
#define SMEM_FLOATS (XS_FLOATS + 2*HK_BUF)   // 33664 floats = 134656 B

static __device__ __forceinline__ ull fma2(ull a, ull b, ull c) {
    ull d;
    asm("fma.rn.f32x2 %0, %1, %2, %3;" : "=l"(d) : "l"(a), "l"(b), "l"(c));
    return d;
}

__global__ __launch_bounds__(THREADS, 1)
void had_fused_kernel(const float* __restrict__ x,
                      const float* __restrict__ hK,
                      float* __restrict__ out,
                      int nrows)
{
    extern __shared__ float smem[];
    float* xs  = smem;              // [22272]
    float* hkd = smem + XS_FLOATS;  // [2][5696]

    const int tid  = threadIdx.x;
    const int row0 = blockIdx.x * 2;
    const int nr   = (nrows - row0 >= 2) ? 2 : (nrows - row0); // rows handled here

    // ---------------- Phase 1: load x rows into smem ----------------
    {
        const float4* src = (const float4*)(x + (size_t)row0 * D_DIM);
        float4* dst = (float4*)xs;
        const int n4 = nr * (D_DIM / 4);
        for (int i = tid; i < n4; i += THREADS) dst[i] = src[i];
        // zero any unloaded region + pad (j-padding reads must be 0, not NaN)
        for (int i = nr * D_DIM + tid; i < XS_FLOATS; i += THREADS) xs[i] = 0.f;
    }

    // prefetch had_K tile 0 into registers (overlaps with x load latency)
    float pre[6];
    {
        #pragma unroll
        for (int q = 0; q < 6; ++q) {
            int idx = tid + q * THREADS;
            float v = 0.f;
            if (idx < K_DIM * JT) {
                int i = idx >> 4, jj = idx & 15;          // tile 0: j = jj < 172
                v = hK[i * K_DIM + jj];
            }
            pre[q] = v;
        }
    }
    __syncthreads();

    // ---------------- Phase 2: FWHT-64 per chunk (warp-cooperative) ----------------
    {
        const int w = tid >> 5, l = tid & 31;
        const float scale = rsqrtf((float)D_DIM);
        for (int c = w; c < 2 * K_DIM; c += (THREADS / 32)) {
            float* p = xs + c * 64;
            float v0 = p[l], v1 = p[l + 32];
            float t0 = v0 + v1, t1 = v0 - v1;            // stage h=32 (register)
            #pragma unroll
            for (int h = 1; h <= 16; h <<= 1) {          // stages h=1..16 (shfl)
                float w0 = __shfl_xor_sync(0xffffffffu, t0, h);
                float w1 = __shfl_xor_sync(0xffffffffu, t1, h);
                if (l & h) { t0 = w0 - t0; t1 = w1 - t1; }
                else       { t0 = t0 + w0; t1 = t1 + w1; }
            }
            p[l] = t0 * scale;
            p[l + 32] = t1 * scale;
        }
        // commit prefetched tile 0 (value-duplicated for packed FMA2 broadcast)
        float2* hw = (float2*)hkd;
        #pragma unroll
        for (int q = 0; q < 6; ++q) {
            int idx = tid + q * THREADS;
            if (idx < K_DIM * JT) {
                int i = idx >> 4, jj = idx & 15;
                hw[jj * 177 + i] = make_float2(pre[q], pre[q]);
            }
        }
    }
    __syncthreads();

    // ---------------- Phase 3: out = had_K @ Xf  (register-tiled FFMA2) ----------------
    const int row = tid >> 8;            // 0..1 : which of the 2 rows
    const int u   = tid & 255;
    const int mg  = u & 7;               // m-group: m0 = mg*8
    const int ig  = u >> 3;              // 0..31  : i0 = ig*6 (padded to 192)
    const int i0  = ig * TI;

    ull acc[TI][4];
    #pragma unroll
    for (int t = 0; t < TI; ++t)
        #pragma unroll
        for (int p = 0; p < 4; ++p) acc[t][p] = 0ull;

    const float* xrow = xs + row * D_DIM + mg * TM;

    for (int jt = 0; jt < NT; ++jt) {
        // prefetch next had_K tile (zero-padded past j=171)
        if (jt + 1 < NT) {
            const int j0n = (jt + 1) * JT;
            #pragma unroll
            for (int q = 0; q < 6; ++q) {
                int idx = tid + q * THREADS;
                float v = 0.f;
                if (idx < K_DIM * JT) {
                    int i = idx >> 4, jj = idx & 15, j = j0n + jj;
                    if (j < K_DIM) v = hK[i * K_DIM + j];
                }
                pre[q] = v;
            }
        }
        const float* hb = hkd + (jt & 1) * HK_BUF;
        const int j0 = jt * JT;
        #pragma unroll 4
        for (int jj = 0; jj < JT; ++jj) {
            const float* xp = xrow + (j0 + jj) * 64;
            ulonglong2 xa = *(const ulonglong2*)(xp);       // m0..m0+3 packed
            ulonglong2 xb = *(const ulonglong2*)(xp + 4);   // m0+4..m0+7 packed
            const float* hp = hb + jj * 354 + 2 * i0;       // duplicated scalars
            #pragma unroll
            for (int t = 0; t < TI; ++t) {
                ull h2 = *(const ull*)(hp + 2 * t);         // {h,h}
                acc[t][0] = fma2(h2, xa.x, acc[t][0]);
                acc[t][1] = fma2(h2, xa.y, acc[t][1]);
                acc[t][2] = fma2(h2, xb.x, acc[t][2]);
                acc[t][3] = fma2(h2, xb.y, acc[t][3]);
            }
        }
        // commit next tile to the other buffer
        if (jt + 1 < NT) {
            float2* hw = (float2*)(hkd + ((jt + 1) & 1) * HK_BUF);
            #pragma unroll
            for (int q = 0; q < 6; ++q) {
                int idx = tid + q * THREADS;
                if (idx < K_DIM * JT) {
                    int i = idx >> 4, jj = idx & 15;
                    hw[jj * 177 + i] = make_float2(pre[q], pre[q]);
                }
            }
        }
        __syncthreads();
    }

    // ---------------- epilogue: store ----------------
    if (row0 + row < nrows) {
        float* orow = out + (size_t)(row0 + row) * D_DIM + mg * TM;
        #pragma unroll
        for (int t = 0; t < TI; ++t) {
            int i = i0 + t;
            if (i < K_DIM) {
                ulonglong2 s0, s1;
                s0.x = acc[t][0]; s0.y = acc[t][1];
                s1.x = acc[t][2]; s1.y = acc[t][3];
                *(ulonglong2*)(orow + i * 64)     = s0;
                *(ulonglong2*)(orow + i * 64 + 4) = s1;
            }
        }
    }
}

extern "C" void kernel_launch(void* const* d_in, const int* in_sizes, int n_in,
                              void* d_out, int out_size)
{
    const float* x  = (const float*)d_in[0];
    const float* hK = (const float*)d_in[1];
    int nx = in_sizes[0];
    // defensive: identify had_K by its size (K*K) in case of input-order surprises
    if (n_in > 1 && in_sizes[0] == K_DIM * K_DIM) {
        x  = (const float*)d_in[1];
        hK = (const float*)d_in[0];
        nx = in_sizes[1];
    }
    float* out = (float*)d_out;

    const int nrows = nx / D_DIM;
    const int ncta  = (nrows + 1) / 2;
    const size_t smem = SMEM_FLOATS * sizeof(float);   // 134656 B

    cudaFuncSetAttribute(had_fused_kernel,
                         cudaFuncAttributeMaxDynamicSharedMemorySize, (int)smem);
    had_fused_kernel<<<ncta, THREADS, smem>>>(x, hK, out, nrows);
}

// round 4
// speedup vs baseline: 3.3428x; 3.3428x over previous
#include <cuda_runtime.h>
#include <cstdint>

#define D_DIM   11008
#define K_DIM   172
#define KPAD    176          // logical K padded to 22 blocks of 8
#define MPAD    192          // i padded for warp grid 4 x 48
#define NBLK    22           // k8 blocks
#define BS_PITCH 72          // smem row pitch (conflict-free: gcd-free bank walk)
#define THREADS 256
#define SMEM_BYTES (KPAD * BS_PITCH * 4)   // 50688

// had_K, permuted + tf32-converted: g_hKp[i][b*8 + ph], ph interleave makes
// (a0,a2) and (a1,a3) fragment pairs contiguous 8-byte loads.
__device__ float g_hKp[MPAD * KPAD];

__global__ void prep_hk(const float* __restrict__ hK) {
    int idx = blockIdx.x * blockDim.x + threadIdx.x;
    if (idx >= MPAD * KPAD) return;
    int i = idx / KPAD, s = idx - i * KPAD;    // s = b*8 + ph
    int b = s >> 3, ph = s & 7;
    int qi = (ph & 1) ? ((ph >> 1) + 4) : (ph >> 1);   // invert ph(qi)=2*(qi&3)+(qi>>2)
    int j = b * 8 + qi;
    float v = (i < K_DIM && j < K_DIM) ? hK[i * K_DIM + j] : 0.f;
    uint32_t t;
    asm("cvt.rna.tf32.f32 %0, %1;" : "=r"(t) : "f"(v));
    g_hKp[idx] = __uint_as_float(t);
}

__global__ __launch_bounds__(THREADS, 2)
void had_mma_kernel(const float* __restrict__ x,
                    float* __restrict__ out)
{
    extern __shared__ float Bs[];            // [KPAD][BS_PITCH] tf32 bits
    const int tid  = threadIdx.x;
    const int w    = tid >> 5;
    const int lane = tid & 31;
    const int q    = lane >> 2;              // 0..7
    const int p    = lane & 3;               // 0..3
    const int row  = blockIdx.x;

    // ---------------- Phase 1: FWHT-64 per chunk -> Bs (tf32 bits) ----------------
    {
        const float* xr = x + (size_t)row * D_DIM;
        float v0[NBLK], v1[NBLK];
        #pragma unroll
        for (int k = 0; k < NBLK; ++k) {
            int c = w + 8 * k;                       // chunk / j index
            if (c < K_DIM) { v0[k] = xr[c * 64 + lane]; v1[k] = xr[c * 64 + 32 + lane]; }
            else           { v0[k] = 0.f;             v1[k] = 0.f; }
        }
        const float scale = rsqrtf((float)D_DIM);
        #pragma unroll
        for (int k = 0; k < NBLK; ++k) {
            int c = w + 8 * k;                       // c <= 175 < KPAD always
            float t0 = v0[k] + v1[k], t1 = v0[k] - v1[k];   // stage h=32
            #pragma unroll
            for (int h = 1; h <= 16; h <<= 1) {      // stages h=1..16 via shfl
                float s0 = __shfl_xor_sync(0xffffffffu, t0, h);
                float s1 = __shfl_xor_sync(0xffffffffu, t1, h);
                if (lane & h) { t0 = s0 - t0; t1 = s1 - t1; }
                else          { t0 = t0 + s0; t1 = t1 + s1; }
            }
            t0 *= scale; t1 *= scale;
            uint32_t u0, u1;
            asm("cvt.rna.tf32.f32 %0, %1;" : "=r"(u0) : "f"(t0));
            asm("cvt.rna.tf32.f32 %0, %1;" : "=r"(u1) : "f"(t1));
            Bs[c * BS_PITCH + lane]      = __uint_as_float(u0);  // m = lane
            Bs[c * BS_PITCH + 32 + lane] = __uint_as_float(u1);  // m = lane+32
        }
    }
    __syncthreads();

    // ---------------- Phase 2: C = hK_pad @ Xf via mma.sync tf32 ----------------
    const int mw = w & 3;                    // M-warp: i0 = mw*48
    const int nw = w >> 2;                   // N-warp: m0 = nw*32
    const int i0 = mw * 48;
    const int n0 = nw * 32;

    float acc[3][4][4];
    #pragma unroll
    for (int t = 0; t < 3; ++t)
        #pragma unroll
        for (int u = 0; u < 4; ++u)
            #pragma unroll
            for (int r = 0; r < 4; ++r) acc[t][u][r] = 0.f;

    const float* Ap = g_hKp;

    #pragma unroll 2
    for (int b = 0; b < NBLK; ++b) {
        // B fragments: b0=(k=8b+p, n), b1=(k=8b+p+4, n) — conflict-free LDS
        uint32_t bf0[4], bf1[4];
        const float* br0 = Bs + (8 * b + p) * BS_PITCH + n0 + q;
        const float* br1 = br0 + 4 * BS_PITCH;
        #pragma unroll
        for (int u = 0; u < 4; ++u) {
            bf0[u] = __float_as_uint(br0[u * 8]);
            bf1[u] = __float_as_uint(br1[u * 8]);
        }
        #pragma unroll
        for (int t = 0; t < 3; ++t) {
            const int r0 = i0 + t * 16 + q;
            float2 a02 = *(const float2*)(Ap + (size_t)r0 * KPAD + b * 8 + 2 * p);
            float2 a13 = *(const float2*)(Ap + (size_t)(r0 + 8) * KPAD + b * 8 + 2 * p);
            const uint32_t a0 = __float_as_uint(a02.x), a2 = __float_as_uint(a02.y);
            const uint32_t a1 = __float_as_uint(a13.x), a3 = __float_as_uint(a13.y);
            #pragma unroll
            for (int u = 0; u < 4; ++u) {
                asm volatile(
                    "mma.sync.aligned.m16n8k8.row.col.f32.tf32.tf32.f32 "
                    "{%0,%1,%2,%3}, {%4,%5,%6,%7}, {%8,%9}, {%0,%1,%2,%3};"
                    : "+f"(acc[t][u][0]), "+f"(acc[t][u][1]),
                      "+f"(acc[t][u][2]), "+f"(acc[t][u][3])
                    : "r"(a0), "r"(a1), "r"(a2), "r"(a3),
                      "r"(bf0[u]), "r"(bf1[u]));
            }
        }
    }

    // ---------------- Phase 3: direct coalesced store ----------------
    float* orow = out + (size_t)row * D_DIM;
    #pragma unroll
    for (int t = 0; t < 3; ++t) {
        const int ib = i0 + t * 16 + q;
        #pragma unroll
        for (int u = 0; u < 4; ++u) {
            const int m = n0 + u * 8 + 2 * p;
            if (ib < K_DIM)
                *(float2*)(orow + ib * 64 + m) = make_float2(acc[t][u][0], acc[t][u][1]);
            if (ib + 8 < K_DIM)
                *(float2*)(orow + (ib + 8) * 64 + m) = make_float2(acc[t][u][2], acc[t][u][3]);
        }
    }
}

extern "C" void kernel_launch(void* const* d_in, const int* in_sizes, int n_in,
                              void* d_out, int out_size)
{
    const float* x  = (const float*)d_in[0];
    const float* hK = (const float*)d_in[1];
    int nx = in_sizes[0];
    if (n_in > 1 && in_sizes[0] == K_DIM * K_DIM) {   // defensive input-order check
        x  = (const float*)d_in[1];
        hK = (const float*)d_in[0];
        nx = in_sizes[1];
    }
    float* out = (float*)d_out;
    const int nrows = nx / D_DIM;

    cudaFuncSetAttribute(had_mma_kernel,
                         cudaFuncAttributeMaxDynamicSharedMemorySize, SMEM_BYTES);

    prep_hk<<<(MPAD * KPAD + 255) / 256, 256>>>(hK);
    had_mma_kernel<<<nrows, THREADS, SMEM_BYTES>>>(x, out);
}

// round 5
// speedup vs baseline: 4.4831x; 1.3411x over previous
#include <cuda_runtime.h>
#include <cstdint>

#define D_DIM   11008
#define K_DIM   172
#define KPAD    176          // logical K padded to 22 blocks of 8
#define MPAD    192          // i padded for warp grid 4 x 48
#define NBLK    22           // k8 blocks
#define BS_PITCH 72          // smem row pitch (conflict-free bank walk)
#define OS_PITCH 72          // output staging pitch
#define THREADS 256
#define SMEM_BYTES (KPAD * BS_PITCH * 4)   // 50688 (also >= 172*72*4 = 49536 for staging)

// had_K pre-packed into mma fragment order:
//   block (mw, t, b) -> 32 lanes -> float4 {a0, a1, a2, a3}
//   a0 = hK[i][j],  a1 = hK[i+8][j],  a2 = hK[i][j+4],  a3 = hK[i+8][j+4]
//   with i = mw*48 + t*16 + q, j = 8b + p, q = lane>>2, p = lane&3.
// One LDG.128 per (t,b) per lane -> fully coalesced 512B per warp.
__device__ float4 g_hKp[4 * 3 * NBLK * 32];

__global__ void prep_hk(const float* __restrict__ hK) {
    int idx = blockIdx.x * blockDim.x + threadIdx.x;   // one float4 each
    if (idx >= 4 * 3 * NBLK * 32) return;
    int lane = idx & 31;
    int b    = (idx >> 5) % NBLK;
    int t    = (idx >> 5) / NBLK % 3;
    int mw   = (idx >> 5) / (NBLK * 3);
    int q = lane >> 2, p = lane & 3;
    int i = mw * 48 + t * 16 + q;
    int j = 8 * b + p;
    float v[4];
    #pragma unroll
    for (int e = 0; e < 4; ++e) {
        int ii = i + (e & 1) * 8;          // e: 0->(i,j) 1->(i+8,j) 2->(i,j+4) 3->(i+8,j+4)
        int jj = j + (e >> 1) * 4;
        float f = (ii < K_DIM && jj < K_DIM) ? hK[ii * K_DIM + jj] : 0.f;
        uint32_t u;
        asm("cvt.rna.tf32.f32 %0, %1;" : "=r"(u) : "f"(f));
        v[e] = __uint_as_float(u);
    }
    g_hKp[idx] = make_float4(v[0], v[1], v[2], v[3]);
}

__global__ __launch_bounds__(THREADS, 2)
void had_mma_kernel(const float* __restrict__ x,
                    float* __restrict__ out)
{
    extern __shared__ float Bs[];            // phase2: [KPAD][BS_PITCH]; epilogue: [172][OS_PITCH]
    const int tid  = threadIdx.x;
    const int w    = tid >> 5;
    const int lane = tid & 31;
    const int q    = lane >> 2;              // 0..7
    const int p    = lane & 3;               // 0..3
    const int row  = blockIdx.x;

    // ---------------- Phase 1: FWHT-64 per chunk -> Bs (tf32 bits) ----------------
    {
        const float* xr = x + (size_t)row * D_DIM;
        float v0[NBLK], v1[NBLK];
        #pragma unroll
        for (int k = 0; k < NBLK; ++k) {
            int c = w + 8 * k;
            if (c < K_DIM) { v0[k] = xr[c * 64 + lane]; v1[k] = xr[c * 64 + 32 + lane]; }
            else           { v0[k] = 0.f;               v1[k] = 0.f; }
        }
        const float scale = rsqrtf((float)D_DIM);
        #pragma unroll
        for (int k = 0; k < NBLK; ++k) {
            int c = w + 8 * k;
            float t0 = v0[k] + v1[k], t1 = v0[k] - v1[k];    // stage h=32
            #pragma unroll
            for (int h = 1; h <= 16; h <<= 1) {              // h=1..16 via shfl
                float s0 = __shfl_xor_sync(0xffffffffu, t0, h);
                float s1 = __shfl_xor_sync(0xffffffffu, t1, h);
                if (lane & h) { t0 = s0 - t0; t1 = s1 - t1; }
                else          { t0 = t0 + s0; t1 = t1 + s1; }
            }
            t0 *= scale; t1 *= scale;
            uint32_t u0, u1;
            asm("cvt.rna.tf32.f32 %0, %1;" : "=r"(u0) : "f"(t0));
            asm("cvt.rna.tf32.f32 %0, %1;" : "=r"(u1) : "f"(t1));
            Bs[c * BS_PITCH + lane]      = __uint_as_float(u0);  // m = lane
            Bs[c * BS_PITCH + 32 + lane] = __uint_as_float(u1);  // m = lane+32
        }
    }
    __syncthreads();

    // ---------------- Phase 2: C = hK_pad @ Xf via mma.sync tf32 ----------------
    const int mw = w & 3;                    // i0 = mw*48
    const int nw = w >> 2;                   // m0 = nw*32
    const int n0 = nw * 32;

    float acc[3][4][4];
    #pragma unroll
    for (int t = 0; t < 3; ++t)
        #pragma unroll
        for (int u = 0; u < 4; ++u)
            #pragma unroll
            for (int r = 0; r < 4; ++r) acc[t][u][r] = 0.f;

    const float4* Aw = g_hKp + (size_t)(mw * 3) * NBLK * 32 + lane;

    #pragma unroll 2
    for (int b = 0; b < NBLK; ++b) {
        // B fragments from smem (conflict-free scalar LDS)
        uint32_t bf0[4], bf1[4];
        const float* br0 = Bs + (8 * b + p) * BS_PITCH + n0 + q;
        const float* br1 = br0 + 4 * BS_PITCH;
        #pragma unroll
        for (int u = 0; u < 4; ++u) {
            bf0[u] = __float_as_uint(br0[u * 8]);
            bf1[u] = __float_as_uint(br1[u * 8]);
        }
        #pragma unroll
        for (int t = 0; t < 3; ++t) {
            float4 a = Aw[(size_t)(t * NBLK + b) * 32];     // one LDG.128, coalesced
            const uint32_t a0 = __float_as_uint(a.x), a1 = __float_as_uint(a.y);
            const uint32_t a2 = __float_as_uint(a.z), a3 = __float_as_uint(a.w);
            #pragma unroll
            for (int u = 0; u < 4; ++u) {
                asm volatile(
                    "mma.sync.aligned.m16n8k8.row.col.f32.tf32.tf32.f32 "
                    "{%0,%1,%2,%3}, {%4,%5,%6,%7}, {%8,%9}, {%0,%1,%2,%3};"
                    : "+f"(acc[t][u][0]), "+f"(acc[t][u][1]),
                      "+f"(acc[t][u][2]), "+f"(acc[t][u][3])
                    : "r"(a0), "r"(a1), "r"(a2), "r"(a3),
                      "r"(bf0[u]), "r"(bf1[u]));
            }
        }
    }
    __syncthreads();   // everyone done reading Bs; reuse it as output stage

    // ---------------- Phase 3: stage accumulators -> coalesced store ----------------
    {
        const int i0 = mw * 48;
        #pragma unroll
        for (int t = 0; t < 3; ++t) {
            const int ib = i0 + t * 16 + q;
            #pragma unroll
            for (int u = 0; u < 4; ++u) {
                const int m = n0 + u * 8 + 2 * p;
                if (ib < K_DIM)
                    *(float2*)(Bs + ib * OS_PITCH + m) =
                        make_float2(acc[t][u][0], acc[t][u][1]);
                if (ib + 8 < K_DIM)
                    *(float2*)(Bs + (ib + 8) * OS_PITCH + m) =
                        make_float2(acc[t][u][2], acc[t][u][3]);
            }
        }
    }
    __syncthreads();
    {
        float4* orow4 = (float4*)(out + (size_t)row * D_DIM);
        // 172*64 floats = 2752 float4; conflict-free LDS.128 + coalesced STG.128
        for (int u4 = tid; u4 < (K_DIM * 64) / 4; u4 += THREADS) {
            const int i  = u4 >> 4;
            const int m4 = u4 & 15;
            orow4[u4] = *(const float4*)(Bs + i * OS_PITCH + m4 * 4);
        }
    }
}

extern "C" void kernel_launch(void* const* d_in, const int* in_sizes, int n_in,
                              void* d_out, int out_size)
{
    const float* x  = (const float*)d_in[0];
    const float* hK = (const float*)d_in[1];
    int nx = in_sizes[0];
    if (n_in > 1 && in_sizes[0] == K_DIM * K_DIM) {   // defensive input-order check
        x  = (const float*)d_in[1];
        hK = (const float*)d_in[0];
        nx = in_sizes[1];
    }
    float* out = (float*)d_out;
    const int nrows = nx / D_DIM;

    cudaFuncSetAttribute(had_mma_kernel,
                         cudaFuncAttributeMaxDynamicSharedMemorySize, SMEM_BYTES);

    prep_hk<<<(4 * 3 * NBLK * 32 + 255) / 256, 256>>>(hK);
    had_mma_kernel<<<nrows, THREADS, SMEM_BYTES>>>(x, out);
}